// round 2
// baseline (speedup 1.0000x reference)
#include <cuda_runtime.h>
#include <math_constants.h>

#define NGROUPS 4096
#define NPAIRS  2048
#define DIM     64
#define MM      128
#define PSTR    68    // padded stride for 64-wide tiles
#define SSTR    132   // padded stride for 128-wide tiles

// ---- smem layout (floats) ----
// p1   @ 0       (128*68 = 8704)
// p2   @ 8704    (8704)
// t1   @ 17408   (8704)            (also s2buf base: 128*132=16896 <= 17408)
// t2T  @ 26112   (8704, used 64*132=8448)
// Z    @ 34816   (16896): phase A: h(8704) | W1s(4096) | W2s(4096); phase B: sim(128*132)
// red  @ 51712   : rowmax[128] rowinv[128] colmax[128] colinv[128] b1s[64] b2s[64]
// total = 52352 floats = 209408 bytes
#define SMEM_BYTES  209408

__device__ int g_off[NGROUPS];
__device__ int g_size[NGROUPS];

// Sizes may arrive as int32 or int64 depending on harness dtype handling.
// All sizes are in [1,127], so under int64 LE the odd 32-bit words are 0;
// under int32 they are >= 1. Detect and read accordingly.
__global__ void scan_kernel(const int* __restrict__ raw) {
    __shared__ int wsum[32];
    const int stride =
        (raw[1] == 0 && raw[3] == 0 && raw[5] == 0 && raw[7] == 0) ? 2 : 1;
    int tid = threadIdx.x;              // 1024 threads, 4 items each
    int base = tid * 4;
    int v[4]; int s = 0;
#pragma unroll
    for (int i = 0; i < 4; i++) { v[i] = s; s += raw[(base + i) * stride]; }
    int lane = tid & 31, w = tid >> 5;
    int x = s;
#pragma unroll
    for (int d = 1; d < 32; d <<= 1) { int y = __shfl_up_sync(0xffffffffu, x, d); if (lane >= d) x += y; }
    if (lane == 31) wsum[w] = x;
    int excl = x - s;
    __syncthreads();
    if (w == 0) {
        int ws = wsum[lane]; int xx = ws;
#pragma unroll
        for (int d = 1; d < 32; d <<= 1) { int y = __shfl_up_sync(0xffffffffu, xx, d); if (lane >= d) xx += y; }
        wsum[lane] = xx - ws;
    }
    __syncthreads();
    int off = wsum[w] + excl;
#pragma unroll
    for (int i = 0; i < 4; i++) {
        g_off[base + i]  = off + v[i];
        g_size[base + i] = raw[(base + i) * stride];
    }
}

// out[128x64] = op(A[128x64(PSTR)] @ W[64x64] + bias), optional relu, rows>=nvalid zeroed.
// TROUT: store transposed into O[(n)*ostride + m].
template<bool RELU, bool TROUT>
__device__ __forceinline__ void gemm_128_64(
    const float* __restrict__ A, const float* __restrict__ W,
    const float* __restrict__ bias, float* __restrict__ O,
    int ostride, int nvalid)
{
    const int tx = threadIdx.x & 15, ty = threadIdx.x >> 4;
    const int n0 = tx << 2;
    float acc[8][4];
    const float bx = bias[n0], by = bias[n0 + 1], bz = bias[n0 + 2], bw = bias[n0 + 3];
#pragma unroll
    for (int i = 0; i < 8; i++) { acc[i][0] = bx; acc[i][1] = by; acc[i][2] = bz; acc[i][3] = bw; }
#pragma unroll 8
    for (int k = 0; k < 64; k++) {
        float4 w4 = *(const float4*)(W + k * 64 + n0);
#pragma unroll
        for (int i = 0; i < 8; i++) {
            float a = A[(ty + 16 * i) * PSTR + k];
            acc[i][0] = fmaf(a, w4.x, acc[i][0]);
            acc[i][1] = fmaf(a, w4.y, acc[i][1]);
            acc[i][2] = fmaf(a, w4.z, acc[i][2]);
            acc[i][3] = fmaf(a, w4.w, acc[i][3]);
        }
    }
#pragma unroll
    for (int i = 0; i < 8; i++) {
        int m = ty + 16 * i;
        float o0 = acc[i][0], o1 = acc[i][1], o2 = acc[i][2], o3 = acc[i][3];
        if (RELU) { o0 = fmaxf(o0, 0.f); o1 = fmaxf(o1, 0.f); o2 = fmaxf(o2, 0.f); o3 = fmaxf(o3, 0.f); }
        if (nvalid >= 0 && m >= nvalid) { o0 = 0.f; o1 = 0.f; o2 = 0.f; o3 = 0.f; }
        if (TROUT) {
            O[(n0 + 0) * ostride + m] = o0;
            O[(n0 + 1) * ostride + m] = o1;
            O[(n0 + 2) * ostride + m] = o2;
            O[(n0 + 3) * ostride + m] = o3;
        } else {
            *(float4*)(O + m * ostride + n0) = make_float4(o0, o1, o2, o3);
        }
    }
}

__global__ __launch_bounds__(256) void cross_kernel(
    const float* __restrict__ data, const float* __restrict__ W1g,
    const float* __restrict__ b1g, const float* __restrict__ W2g,
    const float* __restrict__ b2g,
    float* __restrict__ res_out, float* __restrict__ s1_out, float* __restrict__ s2_out)
{
    extern __shared__ float smf[];
    float* p1    = smf;
    float* p2    = smf + 8704;
    float* t1    = smf + 17408;
    float* t2T   = smf + 26112;
    float* s2buf = smf + 17408;     // overlays t1+t2T after sim done
    float* hbuf  = smf + 34816;
    float* W1s   = smf + 43520;
    float* W2s   = smf + 47616;
    float* simb  = smf + 34816;     // overlays hbuf+W after MLPs done
    float* rowmax = smf + 51712;
    float* rowinv = smf + 51840;
    float* colmax = smf + 51968;
    float* colinv = smf + 52096;
    float* b1s    = smf + 52224;
    float* b2s    = smf + 52288;

    const int tid = threadIdx.x;
    const int b   = blockIdx.x;
    const int g1 = 2 * b, g2 = 2 * b + 1;
    const int n1 = g_size[g1], n2 = g_size[g2];
    const int off1 = g_off[g1], off2 = g_off[g2];

    // load weights/biases into smem
    for (int i = tid; i < 4096; i += 256) { W1s[i] = W1g[i]; W2s[i] = W2g[i]; }
    if (tid < 64) { b1s[tid] = b1g[tid]; b2s[tid] = b2g[tid]; }

    // load p1/p2 with zero padding
    for (int it = tid; it < MM * 16; it += 256) {
        int r = it >> 4, c4 = (it & 15) << 2;
        float4 z = make_float4(0.f, 0.f, 0.f, 0.f);
        float4 v1 = (r < n1) ? *(const float4*)(data + (size_t)(off1 + r) * DIM + c4) : z;
        float4 v2 = (r < n2) ? *(const float4*)(data + (size_t)(off2 + r) * DIM + c4) : z;
        *(float4*)(p1 + r * PSTR + c4) = v1;
        *(float4*)(p2 + r * PSTR + c4) = v2;
    }
    __syncthreads();

    // t1 = mask(relu(p1@W1+b1)@W2+b2)
    gemm_128_64<true, false>(p1, W1s, b1s, hbuf, PSTR, -1);
    __syncthreads();
    gemm_128_64<false, false>(hbuf, W2s, b2s, t1, PSTR, n1);
    __syncthreads();
    // t2T = mask(relu(p2@W1+b1)@W2+b2) transposed
    gemm_128_64<true, false>(p2, W1s, b1s, hbuf, PSTR, -1);
    __syncthreads();
    gemm_128_64<false, true>(hbuf, W2s, b2s, t2T, SSTR, n2);
    __syncthreads();

    // sim[m][n] = sum_k t1[m][k]*t2[n][k], xor-mask -> -inf
    {
        const int tx = tid & 31, ty = tid >> 5;
        const int n0 = tx << 2;
        float acc[16][4];
#pragma unroll
        for (int i = 0; i < 16; i++) { acc[i][0] = 0.f; acc[i][1] = 0.f; acc[i][2] = 0.f; acc[i][3] = 0.f; }
#pragma unroll 4
        for (int k = 0; k < 64; k++) {
            float4 w4 = *(const float4*)(t2T + k * SSTR + n0);
#pragma unroll
            for (int i = 0; i < 16; i++) {
                float a = t1[(ty * 16 + i) * PSTR + k];
                acc[i][0] = fmaf(a, w4.x, acc[i][0]);
                acc[i][1] = fmaf(a, w4.y, acc[i][1]);
                acc[i][2] = fmaf(a, w4.z, acc[i][2]);
                acc[i][3] = fmaf(a, w4.w, acc[i][3]);
            }
        }
        const bool vb0 = (n0 + 0) < n2, vb1 = (n0 + 1) < n2, vb2 = (n0 + 2) < n2, vb3 = (n0 + 3) < n2;
#pragma unroll
        for (int i = 0; i < 16; i++) {
            int m = ty * 16 + i;
            bool vm = m < n1;
            float o0 = (vm != vb0) ? -CUDART_INF_F : acc[i][0];
            float o1 = (vm != vb1) ? -CUDART_INF_F : acc[i][1];
            float o2 = (vm != vb2) ? -CUDART_INF_F : acc[i][2];
            float o3 = (vm != vb3) ? -CUDART_INF_F : acc[i][3];
            *(float4*)(simb + m * SSTR + n0) = make_float4(o0, o1, o2, o3);
        }
    }
    __syncthreads();

    // row / col max+sum
    if (tid < 128) {
        int r = tid;
        const float* row = simb + r * SSTR;
        float mx = -CUDART_INF_F;
        for (int c4 = 0; c4 < 32; c4++) {
            float4 v = *(const float4*)(row + c4 * 4);
            mx = fmaxf(mx, fmaxf(fmaxf(v.x, v.y), fmaxf(v.z, v.w)));
        }
        float s = 0.f;
        for (int c4 = 0; c4 < 32; c4++) {
            float4 v = *(const float4*)(row + c4 * 4);
            s += __expf(v.x - mx) + __expf(v.y - mx) + __expf(v.z - mx) + __expf(v.w - mx);
        }
        rowmax[r] = mx; rowinv[r] = 1.f / s;
    } else {
        int c = tid - 128;
        float mx = -CUDART_INF_F;
        for (int r = 0; r < 128; r++) mx = fmaxf(mx, simb[r * SSTR + c]);
        float s = 0.f;
        for (int r = 0; r < 128; r++) s += __expf(simb[r * SSTR + c] - mx);
        colmax[c] = mx; colinv[c] = 1.f / s;
    }
    __syncthreads();

    // s1 (in-place over sim) and s2 (into s2buf); stream both to gmem
    for (int it = tid; it < MM * 32; it += 256) {
        int m = it >> 5, n0 = (it & 31) << 2;
        float4 v = *(const float4*)(simb + m * SSTR + n0);
        float rm = rowmax[m], ri = rowinv[m];
        float4 cm = *(const float4*)(colmax + n0);
        float4 ci = *(const float4*)(colinv + n0);
        float4 a, c;
        a.x = __expf(v.x - rm) * ri; a.y = __expf(v.y - rm) * ri;
        a.z = __expf(v.z - rm) * ri; a.w = __expf(v.w - rm) * ri;
        c.x = __expf(v.x - cm.x) * ci.x; c.y = __expf(v.y - cm.y) * ci.y;
        c.z = __expf(v.z - cm.z) * ci.z; c.w = __expf(v.w - cm.w) * ci.w;
        size_t go = (size_t)b * (MM * MM) + (size_t)m * MM + n0;
        *(float4*)(s1_out + go) = a;
        *(float4*)(s2_out + go) = c;
        *(float4*)(simb + m * SSTR + n0) = a;
        *(float4*)(s2buf + m * SSTR + n0) = c;
    }
    __syncthreads();

    // query_new = s1 @ p2 ; corpus_new = s2^T @ p1 — write gathered rows only
    {
        const int tx = tid & 15, ty = tid >> 4;
        const int d0 = tx << 2;
        float acc[8][4];
#pragma unroll
        for (int i = 0; i < 8; i++) { acc[i][0] = 0.f; acc[i][1] = 0.f; acc[i][2] = 0.f; acc[i][3] = 0.f; }
#pragma unroll 4
        for (int n = 0; n < 128; n++) {
            float4 pv = *(const float4*)(p2 + n * PSTR + d0);
#pragma unroll
            for (int i = 0; i < 8; i++) {
                float a = simb[(ty + 16 * i) * SSTR + n];
                acc[i][0] = fmaf(a, pv.x, acc[i][0]);
                acc[i][1] = fmaf(a, pv.y, acc[i][1]);
                acc[i][2] = fmaf(a, pv.z, acc[i][2]);
                acc[i][3] = fmaf(a, pv.w, acc[i][3]);
            }
        }
#pragma unroll
        for (int i = 0; i < 8; i++) {
            int m = ty + 16 * i;
            if (m < n1)
                *(float4*)(res_out + (size_t)(off1 + m) * DIM + d0) =
                    make_float4(acc[i][0], acc[i][1], acc[i][2], acc[i][3]);
        }

        float acc2[8][4];
#pragma unroll
        for (int i = 0; i < 8; i++) { acc2[i][0] = 0.f; acc2[i][1] = 0.f; acc2[i][2] = 0.f; acc2[i][3] = 0.f; }
#pragma unroll 4
        for (int m = 0; m < 128; m++) {
            float4 pv = *(const float4*)(p1 + m * PSTR + d0);
#pragma unroll
            for (int i = 0; i < 8; i++) {
                float a = s2buf[m * SSTR + ty + 16 * i];
                acc2[i][0] = fmaf(a, pv.x, acc2[i][0]);
                acc2[i][1] = fmaf(a, pv.y, acc2[i][1]);
                acc2[i][2] = fmaf(a, pv.z, acc2[i][2]);
                acc2[i][3] = fmaf(a, pv.w, acc2[i][3]);
            }
        }
#pragma unroll
        for (int i = 0; i < 8; i++) {
            int nn = ty + 16 * i;
            if (nn < n2)
                *(float4*)(res_out + (size_t)(off2 + nn) * DIM + d0) =
                    make_float4(acc2[i][0], acc2[i][1], acc2[i][2], acc2[i][3]);
        }
    }
}

extern "C" void kernel_launch(void* const* d_in, const int* in_sizes, int n_in,
                              void* d_out, int out_size) {
    const float* data = (const float*)d_in[0];
    const float* W1   = (const float*)d_in[1];
    const float* b1   = (const float*)d_in[2];
    const float* W2   = (const float*)d_in[3];
    const float* b2   = (const float*)d_in[4];
    const int*   sizes_raw = (const int*)d_in[5];

    float* out = (float*)d_out;
    size_t total_e = (size_t)in_sizes[0];        // total * DIM
    float* s1o = out + total_e;
    float* s2o = s1o + (size_t)NPAIRS * MM * MM;

    cudaFuncSetAttribute(cross_kernel, cudaFuncAttributeMaxDynamicSharedMemorySize, SMEM_BYTES);

    scan_kernel<<<1, 1024>>>(sizes_raw);
    cross_kernel<<<NPAIRS, 256, SMEM_BYTES>>>(data, W1, b1, W2, b2, out, s1o, s2o);
}

// round 3
// speedup vs baseline: 1.5651x; 1.5651x over previous
#include <cuda_runtime.h>
#include <math_constants.h>

#define NGROUPS 4096
#define NPAIRS  2048
#define DIM     64
#define MM      128
#define PSTR    68    // padded stride for 64-wide tiles
#define SSTR    132   // padded stride for 128-wide tiles
#define NTHREADS 512

// ---- smem layout (floats) ---- (unchanged from R2)
#define SMEM_BYTES  209408

__device__ int g_off[NGROUPS];
__device__ int g_size[NGROUPS];

// sizes may be int32 or int64 (LE); sizes are in [1,127] so int64 odd words are 0.
__global__ void scan_kernel(const int* __restrict__ raw) {
    __shared__ int wsum[32];
    const int stride =
        (raw[1] == 0 && raw[3] == 0 && raw[5] == 0 && raw[7] == 0) ? 2 : 1;
    int tid = threadIdx.x;              // 1024 threads, 4 items each
    int base = tid * 4;
    int v[4]; int s = 0;
#pragma unroll
    for (int i = 0; i < 4; i++) { v[i] = s; s += raw[(base + i) * stride]; }
    int lane = tid & 31, w = tid >> 5;
    int x = s;
#pragma unroll
    for (int d = 1; d < 32; d <<= 1) { int y = __shfl_up_sync(0xffffffffu, x, d); if (lane >= d) x += y; }
    if (lane == 31) wsum[w] = x;
    int excl = x - s;
    __syncthreads();
    if (w == 0) {
        int ws = wsum[lane]; int xx = ws;
#pragma unroll
        for (int d = 1; d < 32; d <<= 1) { int y = __shfl_up_sync(0xffffffffu, xx, d); if (lane >= d) xx += y; }
        wsum[lane] = xx - ws;
    }
    __syncthreads();
    int off = wsum[w] + excl;
#pragma unroll
    for (int i = 0; i < 4; i++) {
        g_off[base + i]  = off + v[i];
        g_size[base + i] = raw[(base + i) * stride];
    }
}

// O[rows x 64] = op(A[rows x 64(PSTR)] @ W[64x64] + bias). 512 threads.
// Each thread: 4 consecutive rows (ty*4..+3) x 4 cols (tx*4..+3).
// Rows >= nrows skipped entirely; rows >= nvalid (if >=0) zeroed.
template<bool RELU, bool TROUT>
__device__ __forceinline__ void gemm_mlp(
    const float* __restrict__ A, const float* __restrict__ W,
    const float* __restrict__ bias, float* __restrict__ O,
    int ostride, int nrows, int nvalid)
{
    const int tx = threadIdx.x & 15, ty = threadIdx.x >> 4;
    const int r0 = ty << 2;
    if (r0 >= nrows) return;
    const int n0 = tx << 2;
    float acc[4][4];
    const float bx = bias[n0], by = bias[n0 + 1], bz = bias[n0 + 2], bw = bias[n0 + 3];
#pragma unroll
    for (int i = 0; i < 4; i++) { acc[i][0] = bx; acc[i][1] = by; acc[i][2] = bz; acc[i][3] = bw; }
#pragma unroll 8
    for (int k = 0; k < 64; k++) {
        float4 w4 = *(const float4*)(W + k * 64 + n0);
#pragma unroll
        for (int i = 0; i < 4; i++) {
            float a = A[(r0 + i) * PSTR + k];
            acc[i][0] = fmaf(a, w4.x, acc[i][0]);
            acc[i][1] = fmaf(a, w4.y, acc[i][1]);
            acc[i][2] = fmaf(a, w4.z, acc[i][2]);
            acc[i][3] = fmaf(a, w4.w, acc[i][3]);
        }
    }
#pragma unroll
    for (int i = 0; i < 4; i++) {
        int m = r0 + i;
        float o0 = acc[i][0], o1 = acc[i][1], o2 = acc[i][2], o3 = acc[i][3];
        if (RELU) { o0 = fmaxf(o0, 0.f); o1 = fmaxf(o1, 0.f); o2 = fmaxf(o2, 0.f); o3 = fmaxf(o3, 0.f); }
        if (nvalid >= 0 && m >= nvalid) { o0 = 0.f; o1 = 0.f; o2 = 0.f; o3 = 0.f; }
        if (TROUT) {
            O[(n0 + 0) * ostride + m] = o0;
            O[(n0 + 1) * ostride + m] = o1;
            O[(n0 + 2) * ostride + m] = o2;
            O[(n0 + 3) * ostride + m] = o3;
        } else {
            *(float4*)(O + m * ostride + n0) = make_float4(o0, o1, o2, o3);
        }
    }
}

__global__ __launch_bounds__(NTHREADS) void cross_kernel(
    const float* __restrict__ data, const float* __restrict__ W1g,
    const float* __restrict__ b1g, const float* __restrict__ W2g,
    const float* __restrict__ b2g,
    float* __restrict__ res_out, float* __restrict__ s1_out, float* __restrict__ s2_out)
{
    extern __shared__ float smf[];
    float* p1    = smf;
    float* p2    = smf + 8704;
    float* t1    = smf + 17408;
    float* t2T   = smf + 26112;
    float* s2buf = smf + 17408;     // overlays t1+t2T after sim done
    float* hbuf  = smf + 34816;
    float* W1s   = smf + 43520;
    float* W2s   = smf + 47616;
    float* simb  = smf + 34816;     // overlays hbuf+W after MLPs done
    float* rowmax = smf + 51712;
    float* rowinv = smf + 51840;
    float* colmax = smf + 51968;
    float* colinv = smf + 52096;
    float* b1s    = smf + 52224;
    float* b2s    = smf + 52288;

    const int tid = threadIdx.x;
    const int b   = blockIdx.x;
    const int g1 = 2 * b, g2 = 2 * b + 1;
    const int n1 = g_size[g1], n2 = g_size[g2];
    const int off1 = g_off[g1], off2 = g_off[g2];

    // load weights/biases
    for (int i = tid; i < 4096; i += NTHREADS) { W1s[i] = W1g[i]; W2s[i] = W2g[i]; }
    if (tid < 64) { b1s[tid] = b1g[tid]; b2s[tid] = b2g[tid]; }

    // load p1/p2 with zero padding
    for (int it = tid; it < MM * 16; it += NTHREADS) {
        int r = it >> 4, c4 = (it & 15) << 2;
        float4 z = make_float4(0.f, 0.f, 0.f, 0.f);
        float4 v1 = (r < n1) ? *(const float4*)(data + (size_t)(off1 + r) * DIM + c4) : z;
        float4 v2 = (r < n2) ? *(const float4*)(data + (size_t)(off2 + r) * DIM + c4) : z;
        *(float4*)(p1 + r * PSTR + c4) = v1;
        *(float4*)(p2 + r * PSTR + c4) = v2;
    }
    __syncthreads();

    // t1 = mask(relu(p1@W1+b1)@W2+b2) — only rows < n1 matter
    gemm_mlp<true, false>(p1, W1s, b1s, hbuf, PSTR, n1, -1);
    __syncthreads();
    gemm_mlp<false, false>(hbuf, W2s, b2s, t1, PSTR, n1, n1);
    __syncthreads();
    // t2T (transposed) — only rows < n2 matter
    gemm_mlp<true, false>(p2, W1s, b1s, hbuf, PSTR, n2, -1);
    __syncthreads();
    gemm_mlp<false, true>(hbuf, W2s, b2s, t2T, SSTR, n2, n2);
    __syncthreads();

    // sim[m][n] for m < n1 (8-row warp-uniform granularity), all 128 cols.
    {
        const int tx = tid & 31, ty = tid >> 5;   // ty in [0,16)
        const int r0 = ty << 3;
        if (r0 < n1) {
            const int n0 = tx << 2;
            float acc[8][4];
#pragma unroll
            for (int i = 0; i < 8; i++) { acc[i][0] = 0.f; acc[i][1] = 0.f; acc[i][2] = 0.f; acc[i][3] = 0.f; }
#pragma unroll 4
            for (int k = 0; k < 64; k++) {
                float4 w4 = *(const float4*)(t2T + k * SSTR + n0);
#pragma unroll
                for (int i = 0; i < 8; i++) {
                    float a = t1[(r0 + i) * PSTR + k];
                    acc[i][0] = fmaf(a, w4.x, acc[i][0]);
                    acc[i][1] = fmaf(a, w4.y, acc[i][1]);
                    acc[i][2] = fmaf(a, w4.z, acc[i][2]);
                    acc[i][3] = fmaf(a, w4.w, acc[i][3]);
                }
            }
            const bool vb0 = (n0 + 0) < n2, vb1 = (n0 + 1) < n2, vb2 = (n0 + 2) < n2, vb3 = (n0 + 3) < n2;
#pragma unroll
            for (int i = 0; i < 8; i++) {
                int m = r0 + i;
                bool vm = m < n1;
                float o0 = (vm != vb0) ? -CUDART_INF_F : acc[i][0];
                float o1 = (vm != vb1) ? -CUDART_INF_F : acc[i][1];
                float o2 = (vm != vb2) ? -CUDART_INF_F : acc[i][2];
                float o3 = (vm != vb3) ? -CUDART_INF_F : acc[i][3];
                *(float4*)(simb + m * SSTR + n0) = make_float4(o0, o1, o2, o3);
            }
        }
    }
    __syncthreads();

    // row / col stats over the valid region only
    if (tid < 128) {
        int r = tid;
        if (r < n1) {
            const float* row = simb + r * SSTR;
            int c4e = (n2 + 3) >> 2;
            float mx = -CUDART_INF_F;
            for (int c4 = 0; c4 < c4e; c4++) {
                float4 v = *(const float4*)(row + c4 * 4);
                mx = fmaxf(mx, fmaxf(fmaxf(v.x, v.y), fmaxf(v.z, v.w)));
            }
            float s = 0.f;
            for (int c4 = 0; c4 < c4e; c4++) {
                float4 v = *(const float4*)(row + c4 * 4);
                s += __expf(v.x - mx) + __expf(v.y - mx) + __expf(v.z - mx) + __expf(v.w - mx);
            }
            rowmax[r] = mx; rowinv[r] = 1.f / s;
        } else { rowmax[r] = 0.f; rowinv[r] = 0.f; }
    } else if (tid < 256) {
        int c = tid - 128;
        if (c < n2) {
            float mx = -CUDART_INF_F;
            for (int r = 0; r < n1; r++) mx = fmaxf(mx, simb[r * SSTR + c]);
            float s = 0.f;
            for (int r = 0; r < n1; r++) s += __expf(simb[r * SSTR + c] - mx);
            colmax[c] = mx; colinv[c] = 1.f / s;
        } else { colmax[c] = 0.f; colinv[c] = 0.f; }
    }
    __syncthreads();

    // materialize s1/s2 (valid region from sim, invalid region analytic), write gmem + smem
    {
        const float inv1 = 1.f / (float)(MM - n1);   // s2 value in both-invalid region
        const float inv2 = 1.f / (float)(MM - n2);   // s1 value in both-invalid region
        for (int it = tid; it < MM * 32; it += NTHREADS) {
            int m = it >> 5, n0 = (it & 31) << 2;
            float4 a, c;
            if (m < n1) {
                float4 v = *(const float4*)(simb + m * SSTR + n0);
                float rm = rowmax[m], ri = rowinv[m];
                float4 cm = *(const float4*)(colmax + n0);
                float4 ci = *(const float4*)(colinv + n0);
                a.x = (n0 + 0 < n2) ? __expf(v.x - rm) * ri : 0.f;
                a.y = (n0 + 1 < n2) ? __expf(v.y - rm) * ri : 0.f;
                a.z = (n0 + 2 < n2) ? __expf(v.z - rm) * ri : 0.f;
                a.w = (n0 + 3 < n2) ? __expf(v.w - rm) * ri : 0.f;
                c.x = (n0 + 0 < n2) ? __expf(v.x - cm.x) * ci.x : 0.f;
                c.y = (n0 + 1 < n2) ? __expf(v.y - cm.y) * ci.y : 0.f;
                c.z = (n0 + 2 < n2) ? __expf(v.z - cm.z) * ci.z : 0.f;
                c.w = (n0 + 3 < n2) ? __expf(v.w - cm.w) * ci.w : 0.f;
            } else {
                a.x = (n0 + 0 < n2) ? 0.f : inv2;
                a.y = (n0 + 1 < n2) ? 0.f : inv2;
                a.z = (n0 + 2 < n2) ? 0.f : inv2;
                a.w = (n0 + 3 < n2) ? 0.f : inv2;
                c.x = (n0 + 0 < n2) ? 0.f : inv1;
                c.y = (n0 + 1 < n2) ? 0.f : inv1;
                c.z = (n0 + 2 < n2) ? 0.f : inv1;
                c.w = (n0 + 3 < n2) ? 0.f : inv1;
            }
            size_t go = (size_t)b * (MM * MM) + (size_t)m * MM + n0;
            *(float4*)(s1_out + go) = a;
            *(float4*)(s2_out + go) = c;
            *(float4*)(simb + m * SSTR + n0) = a;
            *(float4*)(s2buf + m * SSTR + n0) = c;
        }
    }
    __syncthreads();

    // query_new[m<n1] = sum_{n<n2} s1[m][n] p2[n]; corpus_new[nn<n2] = sum_{m<n1} s2[m][nn] p1[m]
    {
        const int tx = tid & 15, ty = tid >> 4;   // ty in [0,32)
        const int d0 = tx << 2;
        const int r0 = ty << 2;
        if (r0 < n1) {
            float acc[4][4];
#pragma unroll
            for (int i = 0; i < 4; i++) { acc[i][0] = 0.f; acc[i][1] = 0.f; acc[i][2] = 0.f; acc[i][3] = 0.f; }
#pragma unroll 4
            for (int n = 0; n < n2; n++) {
                float4 pv = *(const float4*)(p2 + n * PSTR + d0);
#pragma unroll
                for (int i = 0; i < 4; i++) {
                    float a = simb[(r0 + i) * SSTR + n];
                    acc[i][0] = fmaf(a, pv.x, acc[i][0]);
                    acc[i][1] = fmaf(a, pv.y, acc[i][1]);
                    acc[i][2] = fmaf(a, pv.z, acc[i][2]);
                    acc[i][3] = fmaf(a, pv.w, acc[i][3]);
                }
            }
#pragma unroll
            for (int i = 0; i < 4; i++) {
                int m = r0 + i;
                if (m < n1)
                    *(float4*)(res_out + (size_t)(off1 + m) * DIM + d0) =
                        make_float4(acc[i][0], acc[i][1], acc[i][2], acc[i][3]);
            }
        }
        if (r0 < n2) {
            float acc2[4][4];
#pragma unroll
            for (int i = 0; i < 4; i++) { acc2[i][0] = 0.f; acc2[i][1] = 0.f; acc2[i][2] = 0.f; acc2[i][3] = 0.f; }
#pragma unroll 4
            for (int m = 0; m < n1; m++) {
                float4 pv = *(const float4*)(p1 + m * PSTR + d0);
#pragma unroll
                for (int i = 0; i < 4; i++) {
                    float a = s2buf[m * SSTR + r0 + i];
                    acc2[i][0] = fmaf(a, pv.x, acc2[i][0]);
                    acc2[i][1] = fmaf(a, pv.y, acc2[i][1]);
                    acc2[i][2] = fmaf(a, pv.z, acc2[i][2]);
                    acc2[i][3] = fmaf(a, pv.w, acc2[i][3]);
                }
            }
#pragma unroll
            for (int i = 0; i < 4; i++) {
                int nn = r0 + i;
                if (nn < n2)
                    *(float4*)(res_out + (size_t)(off2 + nn) * DIM + d0) =
                        make_float4(acc2[i][0], acc2[i][1], acc2[i][2], acc2[i][3]);
            }
        }
    }
}

extern "C" void kernel_launch(void* const* d_in, const int* in_sizes, int n_in,
                              void* d_out, int out_size) {
    const float* data = (const float*)d_in[0];
    const float* W1   = (const float*)d_in[1];
    const float* b1   = (const float*)d_in[2];
    const float* W2   = (const float*)d_in[3];
    const float* b2   = (const float*)d_in[4];
    const int*   sizes_raw = (const int*)d_in[5];

    float* out = (float*)d_out;
    size_t total_e = (size_t)in_sizes[0];        // total * DIM
    float* s1o = out + total_e;
    float* s2o = s1o + (size_t)NPAIRS * MM * MM;

    cudaFuncSetAttribute(cross_kernel, cudaFuncAttributeMaxDynamicSharedMemorySize, SMEM_BYTES);

    scan_kernel<<<1, 1024>>>(sizes_raw);
    cross_kernel<<<NPAIRS, NTHREADS, SMEM_BYTES>>>(data, W1, b1, W2, b2, out, s1o, s2o);
}